// round 6
// baseline (speedup 1.0000x reference)
#include <cuda_runtime.h>
#include <cuda_bf16.h>

#define N_NEURONS   100000
#define INPUT_SIZE  1024
#define OUTPUT_SIZE 256
#define E_EDGES     10000000
#define STEPS       3

// Persistent state in __device__ globals (no allocation allowed).
__device__ float g_v[N_NEURONS];    // current neuron values
__device__ float g_acc[N_NEURONS];  // accumulator, pre-seeded with biases

// ---------------------------------------------------------------------------
// Init: v = [x, 0...], acc = [0..., biases]
// ---------------------------------------------------------------------------
__global__ void init_kernel(const float* __restrict__ x,
                            const float* __restrict__ bias) {
    int i = blockIdx.x * blockDim.x + threadIdx.x;
    if (i < N_NEURONS) {
        g_v[i]   = (i < INPUT_SIZE) ? x[i] : 0.0f;
        g_acc[i] = (i < INPUT_SIZE) ? 0.0f : bias[i - INPUT_SIZE];
    }
}

// ---------------------------------------------------------------------------
// Edge pass: acc[dst] += v[src] * w, 4 edges per thread via 16B vector loads.
// E = 10,000,000 is divisible by 4.
// ---------------------------------------------------------------------------
__global__ void __launch_bounds__(256)
edge_kernel(const float* __restrict__ w,
            const int*   __restrict__ src,
            const int*   __restrict__ dst) {
    const int nvec = E_EDGES / 4;
    int i = blockIdx.x * blockDim.x + threadIdx.x;
    if (i >= nvec) return;

    const int4*   src4 = (const int4*)src;
    const int4*   dst4 = (const int4*)dst;
    const float4* w4   = (const float4*)w;

    int4   s  = __ldg(&src4[i]);
    int4   d  = __ldg(&dst4[i]);
    float4 ww = __ldg(&w4[i]);

    float v0 = __ldg(&g_v[s.x]);
    float v1 = __ldg(&g_v[s.y]);
    float v2 = __ldg(&g_v[s.z]);
    float v3 = __ldg(&g_v[s.w]);

    atomicAdd(&g_acc[d.x], v0 * ww.x);
    atomicAdd(&g_acc[d.y], v1 * ww.y);
    atomicAdd(&g_acc[d.z], v2 * ww.z);
    atomicAdd(&g_acc[d.w], v3 * ww.w);
}

// ---------------------------------------------------------------------------
// Post pass: v = tanh(acc) (except outputs), re-seed acc with biases,
// optionally emit the output slice.
// ---------------------------------------------------------------------------
__global__ void post_kernel(const float* __restrict__ bias,
                            float* __restrict__ out,
                            int write_out) {
    int i = blockIdx.x * blockDim.x + threadIdx.x;
    if (i < N_NEURONS) {
        float a = g_acc[i];
        float v = (i < N_NEURONS - OUTPUT_SIZE) ? tanhf(a) : a;
        g_v[i]   = v;
        g_acc[i] = (i < INPUT_SIZE) ? 0.0f : bias[i - INPUT_SIZE];
        if (write_out && i >= N_NEURONS - OUTPUT_SIZE) {
            out[i - (N_NEURONS - OUTPUT_SIZE)] = v;
        }
    }
}

// ---------------------------------------------------------------------------
// Launcher — graph-capturable: kernel launches only.
// Input order (metadata.txt): x, synapse_weights, neuron_biases,
//                             synapse_src, synapse_dst
// ---------------------------------------------------------------------------
extern "C" void kernel_launch(void* const* d_in, const int* in_sizes, int n_in,
                              void* d_out, int out_size) {
    const float* x    = (const float*)d_in[0];
    const float* w    = (const float*)d_in[1];
    const float* bias = (const float*)d_in[2];
    const int*   src  = (const int*)d_in[3];
    const int*   dst  = (const int*)d_in[4];
    float* out = (float*)d_out;

    const int tpbN = 256;
    const int gridN = (N_NEURONS + tpbN - 1) / tpbN;

    const int nvec = E_EDGES / 4;
    const int tpbE = 256;
    const int gridE = (nvec + tpbE - 1) / tpbE;

    init_kernel<<<gridN, tpbN>>>(x, bias);
    for (int step = 0; step < STEPS; ++step) {
        edge_kernel<<<gridE, tpbE>>>(w, src, dst);
        post_kernel<<<gridN, tpbN>>>(bias, out, step == STEPS - 1 ? 1 : 0);
    }
}

// round 7
// speedup vs baseline: 1.2438x; 1.2438x over previous
#include <cuda_runtime.h>
#include <cuda_bf16.h>

#define N_NEURONS   100000
#define INPUT_SIZE  1024
#define OUTPUT_SIZE 256
#define E_EDGES     10000000
#define STEPS       3

#define CHUNK       50000            // floats of v per smem chunk (200 KB)
#define NCHUNKS     2
#define SMEM_BYTES  (CHUNK * 4)

// Persistent state in __device__ globals (no allocation allowed).
__device__ float g_v[N_NEURONS];    // current neuron values
__device__ float g_acc[N_NEURONS];  // accumulator, pre-seeded with biases

// ---------------------------------------------------------------------------
// Init: acc = [0..., biases].  (g_v is written by post before it is ever read:
// step-1 gathers directly from x.)
// ---------------------------------------------------------------------------
__global__ void init_kernel(const float* __restrict__ bias) {
    int i = blockIdx.x * blockDim.x + threadIdx.x;
    if (i < N_NEURONS) {
        g_acc[i] = (i < INPUT_SIZE) ? 0.0f : bias[i - INPUT_SIZE];
    }
}

// ---------------------------------------------------------------------------
// Step-1 edge pass: v is zero except v[0:1024] = x, so only edges with
// src < INPUT_SIZE contribute (~1% of E). Stream src only; touch w/dst/acc
// only for live edges (scalar predicated loads -> wavefronts only where live).
// ---------------------------------------------------------------------------
__global__ void __launch_bounds__(256)
edge_step1_kernel(const float* __restrict__ x,
                  const float* __restrict__ w,
                  const int*   __restrict__ src,
                  const int*   __restrict__ dst) {
    const int nvec = E_EDGES / 4;
    int i = blockIdx.x * blockDim.x + threadIdx.x;
    if (i >= nvec) return;

    int4 s = __ldg(&((const int4*)src)[i]);
    int  e = i * 4;

    if (s.x < INPUT_SIZE) {
        float m = __ldg(&x[s.x]) * __ldg(&w[e + 0]);
        atomicAdd(&g_acc[__ldg(&dst[e + 0])], m);
    }
    if (s.y < INPUT_SIZE) {
        float m = __ldg(&x[s.y]) * __ldg(&w[e + 1]);
        atomicAdd(&g_acc[__ldg(&dst[e + 1])], m);
    }
    if (s.z < INPUT_SIZE) {
        float m = __ldg(&x[s.z]) * __ldg(&w[e + 2]);
        atomicAdd(&g_acc[__ldg(&dst[e + 2])], m);
    }
    if (s.w < INPUT_SIZE) {
        float m = __ldg(&x[s.w]) * __ldg(&w[e + 3]);
        atomicAdd(&g_acc[__ldg(&dst[e + 3])], m);
    }
}

// ---------------------------------------------------------------------------
// Steps 2-3 edge pass: persistent CTAs; v served from shared memory in
// NCHUNKS passes. Replaces 10M one-sector gather LDG wavefronts with LDS.
// acc[dst] += v[src] * w via scattered RED (unavoidable).
// ---------------------------------------------------------------------------
__global__ void __launch_bounds__(1024, 1)
edge_smem_kernel(const float* __restrict__ w,
                 const int*   __restrict__ src,
                 const int*   __restrict__ dst) {
    extern __shared__ float sv[];   // CHUNK floats

    const int4*   src4 = (const int4*)src;
    const int4*   dst4 = (const int4*)dst;
    const float4* w4   = (const float4*)w;
    const int nvec   = E_EDGES / 4;
    const int stride = gridDim.x * blockDim.x;

    for (int c = 0; c < NCHUNKS; ++c) {
        const int base = c * CHUNK;

        // Load this v-chunk into smem (float4 coalesced; CHUNK%4==0, base 16B-aligned)
        {
            const float4* vsrc = (const float4*)(g_v + base);
            float4*       vdst = (float4*)sv;
            for (int j = threadIdx.x; j < CHUNK / 4; j += blockDim.x)
                vdst[j] = vsrc[j];
        }
        __syncthreads();

        for (int i = blockIdx.x * blockDim.x + threadIdx.x; i < nvec; i += stride) {
            int4   s  = __ldg(&src4[i]);
            int4   d  = __ldg(&dst4[i]);
            float4 ww = __ldg(&w4[i]);

            unsigned r0 = (unsigned)(s.x - base);
            unsigned r1 = (unsigned)(s.y - base);
            unsigned r2 = (unsigned)(s.z - base);
            unsigned r3 = (unsigned)(s.w - base);

            if (r0 < CHUNK) atomicAdd(&g_acc[d.x], sv[r0] * ww.x);
            if (r1 < CHUNK) atomicAdd(&g_acc[d.y], sv[r1] * ww.y);
            if (r2 < CHUNK) atomicAdd(&g_acc[d.z], sv[r2] * ww.z);
            if (r3 < CHUNK) atomicAdd(&g_acc[d.w], sv[r3] * ww.w);
        }
        __syncthreads();
    }
}

// ---------------------------------------------------------------------------
// Post pass: v = tanh(acc) (except outputs), re-seed acc with biases,
// optionally emit the output slice.
// ---------------------------------------------------------------------------
__global__ void post_kernel(const float* __restrict__ bias,
                            float* __restrict__ out,
                            int write_out) {
    int i = blockIdx.x * blockDim.x + threadIdx.x;
    if (i < N_NEURONS) {
        float a = g_acc[i];
        float v = (i < N_NEURONS - OUTPUT_SIZE) ? tanhf(a) : a;
        g_v[i]   = v;
        g_acc[i] = (i < INPUT_SIZE) ? 0.0f : bias[i - INPUT_SIZE];
        if (write_out && i >= N_NEURONS - OUTPUT_SIZE) {
            out[i - (N_NEURONS - OUTPUT_SIZE)] = v;
        }
    }
}

// ---------------------------------------------------------------------------
// Launcher — graph-capturable: kernel launches only.
// Input order: x, synapse_weights, neuron_biases, synapse_src, synapse_dst
// ---------------------------------------------------------------------------
extern "C" void kernel_launch(void* const* d_in, const int* in_sizes, int n_in,
                              void* d_out, int out_size) {
    const float* x    = (const float*)d_in[0];
    const float* w    = (const float*)d_in[1];
    const float* bias = (const float*)d_in[2];
    const int*   src  = (const int*)d_in[3];
    const int*   dst  = (const int*)d_in[4];
    float* out = (float*)d_out;

    // Allow 200KB dynamic smem on the persistent edge kernel (idempotent).
    cudaFuncSetAttribute(edge_smem_kernel,
                         cudaFuncAttributeMaxDynamicSharedMemorySize,
                         SMEM_BYTES);

    const int tpbN  = 256;
    const int gridN = (N_NEURONS + tpbN - 1) / tpbN;

    const int nvec  = E_EDGES / 4;
    const int tpbE  = 256;
    const int gridE = (nvec + tpbE - 1) / tpbE;

    init_kernel<<<gridN, tpbN>>>(bias);

    // Step 1: input-sparse edge pass
    edge_step1_kernel<<<gridE, tpbE>>>(x, w, src, dst);
    post_kernel<<<gridN, tpbN>>>(bias, out, 0);

    // Steps 2..3: dense edge pass with smem-resident v
    for (int step = 1; step < STEPS; ++step) {
        edge_smem_kernel<<<148, 1024, SMEM_BYTES>>>(w, src, dst);
        post_kernel<<<gridN, tpbN>>>(bias, out, step == STEPS - 1 ? 1 : 0);
    }
}